// round 14
// baseline (speedup 1.0000x reference)
#include <cuda_runtime.h>
#include <cstdint>

#define Bsz   8
#define Cch   192
#define Himg  224
#define Wimg  224
#define Pw    7
#define NHEAD 6
#define HDIM  32
#define WGRID 32
#define NWIN  1024
#define PPp   49
#define Mrows 401408
#define HWSZ  50176
#define NPROB (Bsz * NWIN * NHEAD)   // 49152

typedef unsigned long long u64t;

static __device__ float g_xw[(size_t)Mrows * Cch];
static __device__ float g_qkv[(size_t)Mrows * 3 * Cch];
static __device__ float g_attn[(size_t)Mrows * Cch];
static __device__ float g_out2[(size_t)Mrows * Cch];
static __device__ float g_wqkv[576 * 192];
static __device__ float g_wout[192 * 192];

// k-permutation within groups of 8: pos = 2*(k&3) + ((k>>2)&1)
__device__ __forceinline__ int kperm(int c) {
    return (c & ~7) | (((c & 3) << 1) | ((c >> 2) & 1));
}

// ───────────────────────── helpers ─────────────────────────
__device__ __forceinline__ uint32_t f2tf(float f) {
    uint32_t u;
    asm("cvt.rna.tf32.f32 %0, %1;" : "=r"(u) : "f"(f));
    return u;
}
__device__ __forceinline__ float f2tf_f(float f) { return __uint_as_float(f2tf(f)); }
__device__ __forceinline__ void mma_m16n8k8(float* c, const uint32_t* a, const uint32_t* b) {
    asm volatile(
        "mma.sync.aligned.m16n8k8.row.col.f32.tf32.tf32.f32 "
        "{%0,%1,%2,%3}, {%4,%5,%6,%7}, {%8,%9}, {%0,%1,%2,%3};"
        : "+f"(c[0]), "+f"(c[1]), "+f"(c[2]), "+f"(c[3])
        : "r"(a[0]), "r"(a[1]), "r"(a[2]), "r"(a[3]), "r"(b[0]), "r"(b[1]));
}
__device__ __forceinline__ void cp16(uint32_t dst, const float* src) {
    asm volatile("cp.async.cg.shared.global [%0], [%1], 16;" :: "r"(dst), "l"(src));
}
#define CP_COMMIT() asm volatile("cp.async.commit_group;" ::: "memory")
#define CP_WAIT(n)  asm volatile("cp.async.wait_group %0;" :: "n"(n) : "memory")

__global__ void k_round(const float* __restrict__ w, float* __restrict__ o, int n) {
    int i = blockIdx.x * 256 + threadIdx.x;
    if (i < n) {
        int row = i / 192, k = i - row * 192;
        o[row * 192 + kperm(k)] = f2tf_f(w[i]);
    }
}

// ───────────────────────── transposes ─────────────────────────
__device__ __forceinline__ int m_of(int b, int hw) {
    int h = hw / Wimg;
    int w = hw - h * Wimg;
    int wi = h / Pw, pi = h - wi * Pw;
    int wj = w / Pw, pj = w - wj * Pw;
    return ((b * WGRID + wi) * WGRID + wj) * PPp + pi * Pw + pj;
}

__global__ void k_gather(const float* __restrict__ x, float* __restrict__ xw) {
    __shared__ float tile[32][33];
    int hw0 = blockIdx.x << 5, c0 = blockIdx.y << 5, b = blockIdx.z;
    int tx = threadIdx.x, ty = threadIdx.y;
    const float* xb = x + (size_t)b * Cch * HWSZ;
#pragma unroll
    for (int it = 0; it < 4; it++) {
        int c = c0 + ty + it * 8;
        tile[ty + it * 8][tx] = xb[(size_t)c * HWSZ + hw0 + tx];
    }
    __syncthreads();
    int cp = kperm(c0 + tx);
#pragma unroll
    for (int it = 0; it < 4; it++) {
        int hw = hw0 + ty + it * 8;
        int m = m_of(b, hw);
        xw[(size_t)m * Cch + cp] = f2tf_f(tile[tx][ty + it * 8]);
    }
}

__global__ void k_scatter(const float* __restrict__ out2, float* __restrict__ out) {
    __shared__ float tile[32][33];
    int hw0 = blockIdx.x << 5, c0 = blockIdx.y << 5, b = blockIdx.z;
    int tx = threadIdx.x, ty = threadIdx.y;
#pragma unroll
    for (int it = 0; it < 4; it++) {
        int hw = hw0 + ty + it * 8;
        int m = m_of(b, hw);
        tile[ty + it * 8][tx] = out2[(size_t)m * Cch + c0 + tx];
    }
    __syncthreads();
    float* ob = out + (size_t)b * Cch * HWSZ;
#pragma unroll
    for (int it = 0; it < 4; it++) {
        int c = c0 + ty + it * 8;
        ob[(size_t)c * HWSZ + hw0 + tx] = tile[tx][ty + it * 8];
    }
}

// ───── TF32 GEMM v5: streaming double-buffer + paired-k LDS.64 ─────
// RPERM=1: epilogue writes tf32-rounded, kperm-permuted columns (for qkv).
#define GBM 128
#define GBN 64
#define GBK 32
#define KTOT 192
#define KTILES 6
#define STR 40
#define A_FL (GBM * STR)
#define B_FL (GBN * STR)
#define GEMM_SMEM (2 * (A_FL + B_FL) * 4)

template <int RPERM>
__global__ void __launch_bounds__(256, 3)
k_gemm_mma(const float* __restrict__ A, const float* __restrict__ Wt,
           const float* __restrict__ bias, float* __restrict__ C, int Ntot) {
    extern __shared__ float smf[];

    int tid = threadIdx.x;
    int wid = tid >> 5, lane = tid & 31;
    int gp = lane >> 2, tg = lane & 3;
    int wm = wid & 3, wn = wid >> 2;
    size_t bm = (size_t)blockIdx.y * GBM;
    int bn = blockIdx.x * GBN;

    uint32_t smb = (uint32_t)__cvta_generic_to_shared(smf);
    int lr = tid >> 3, lq = tid & 7;

    const float* Ag0 = A + (bm + lr) * KTOT + lq * 4;
    const float* Bg  = Wt + (size_t)(bn + lr) * KTOT + lq * 4;
    uint32_t aw = smb + (lr * STR + lq * 4) * 4;
    uint32_t bw = smb + (A_FL + lr * STR + lq * 4) * 4;
    const uint32_t STG = (A_FL + B_FL) * 4;

#define LOAD_T(t, so) do {                                                    \
        int _k0 = (t) * GBK;                                                  \
        _Pragma("unroll")                                                     \
        for (int u = 0; u < 4; u++)                                           \
            cp16(aw + (so) + u * 32 * STR * 4, Ag0 + _k0 + u * 32 * KTOT);    \
        _Pragma("unroll")                                                     \
        for (int u = 0; u < 2; u++)                                           \
            cp16(bw + (so) + u * 32 * STR * 4, Bg + _k0 + u * 32 * KTOT);     \
    } while (0)

    LOAD_T(0, 0);
    CP_COMMIT();

    float acc[2][4][4];
#pragma unroll
    for (int mt = 0; mt < 2; mt++)
#pragma unroll
        for (int nt = 0; nt < 4; nt++)
#pragma unroll
            for (int r = 0; r < 4; r++) acc[mt][nt][r] = 0.f;

    const float* arow0 = smf + (wm * 32 + gp) * STR + 2 * tg;
    const float* brow0 = smf + A_FL + (wn * 32 + gp) * STR + 2 * tg;

#pragma unroll 1
    for (int t = 0; t < KTILES; t++) {
        if (t + 1 < KTILES) {
            LOAD_T(t + 1, ((t + 1) & 1) * STG);
            CP_COMMIT();
            CP_WAIT(1);
        } else {
            CP_WAIT(0);
        }
        __syncthreads();

        const float* as = arow0 + (t & 1) * (STG / 4);
        const float* bs = brow0 + (t & 1) * (STG / 4);
#pragma unroll
        for (int g = 0; g < 4; g++) {
            uint32_t a[2][4], b[4][2];
#pragma unroll
            for (int mt = 0; mt < 2; mt++) {
                const float* p = as + mt * 16 * STR + g * 8;
                float2 v0 = *(const float2*)p;
                float2 v1 = *(const float2*)(p + 8 * STR);
                a[mt][0] = __float_as_uint(v0.x);
                a[mt][2] = __float_as_uint(v0.y);
                a[mt][1] = __float_as_uint(v1.x);
                a[mt][3] = __float_as_uint(v1.y);
            }
#pragma unroll
            for (int nt = 0; nt < 4; nt++) {
                const float* p = bs + nt * 8 * STR + g * 8;
                float2 v = *(const float2*)p;
                b[nt][0] = __float_as_uint(v.x);
                b[nt][1] = __float_as_uint(v.y);
            }
#pragma unroll
            for (int mt = 0; mt < 2; mt++)
#pragma unroll
                for (int nt = 0; nt < 4; nt++)
                    mma_m16n8k8(acc[mt][nt], a[mt], b[nt]);
        }
        __syncthreads();
    }
#undef LOAD_T

#pragma unroll
    for (int mt = 0; mt < 2; mt++) {
        int row = (int)bm + wm * 32 + mt * 16 + gp;
#pragma unroll
        for (int nt = 0; nt < 4; nt++) {
            int col = bn + wn * 32 + nt * 8 + tg * 2;
            float b0 = bias[col], b1 = bias[col + 1];
            if (RPERM) {
                // tf32-round + permute within octet (same 32B sector)
                float* d0 = C + (size_t)row * Ntot;
                float* d1 = C + (size_t)(row + 8) * Ntot;
                int p0 = kperm(col), p1 = kperm(col + 1);
                d0[p0] = f2tf_f(acc[mt][nt][0] + b0);
                d0[p1] = f2tf_f(acc[mt][nt][1] + b1);
                d1[p0] = f2tf_f(acc[mt][nt][2] + b0);
                d1[p1] = f2tf_f(acc[mt][nt][3] + b1);
            } else {
                float2 v0 = make_float2(acc[mt][nt][0] + b0, acc[mt][nt][1] + b1);
                float2 v1 = make_float2(acc[mt][nt][2] + b0, acc[mt][nt][3] + b1);
                *(float2*)(C + (size_t)row * Ntot + col) = v0;
                *(float2*)(C + (size_t)(row + 8) * Ntot + col) = v1;
            }
        }
    }
}

// ───── attention v8: persistent tensor-core, pre-rounded/permuted qkv ─────
#define ATQ 40
#define ATV 72

__global__ void __launch_bounds__(128)
k_attn_mma(const float* __restrict__ qkv, float* __restrict__ attn,
           const float* __restrict__ rel_pos) {
    __shared__ float sq[64 * ATQ];
    __shared__ float sk[64 * ATQ];
    __shared__ float svt[32 * ATV];
    __shared__ float sp[64 * ATV];
    __shared__ float ssb[NHEAD * 176];

    int tid = threadIdx.x;
    int wid = tid >> 5, lane = tid & 31;
    int gp = lane >> 2, tg = lane & 3;
    const float scale = 0.17677669529663687f;

    // one-time init: zero pads + all-head bias
    for (int i = tid; i < 15 * ATQ; i += 128) {
        sq[49 * ATQ + i] = 0.f;
        sk[49 * ATQ + i] = 0.f;
    }
    for (int i = tid; i < 32 * ATV; i += 128) svt[i] = 0.f;
    for (int i = tid; i < NHEAD * 169; i += 128) {
        int h = i / 169, e = i - h * 169;
        ssb[h * 176 + e] = rel_pos[i];
    }

#pragma unroll 1
    for (int blk = blockIdx.x; blk < NPROB; blk += gridDim.x) {
        int head = blk % NHEAD;
        int win = blk / NHEAD;
        int base = win * PPp;
        const size_t rowb = (size_t)base * 576 + head * HDIM;

        __syncthreads();   // previous iteration's readers done

        // qkv already tf32-rounded & d-permuted: direct float4 staging
        for (int idx = tid; idx < PPp * 8; idx += 128) {
            int r = idx >> 3, q8 = idx & 7;
            const float* rowp = qkv + rowb + (size_t)r * 576;
            float4 vq = *((const float4*)rowp + q8);
            float4 vk = *((const float4*)(rowp + 192) + q8);
            float4 vv = *((const float4*)(rowp + 384) + q8);
            *(float4*)(sq + r * ATQ + 4 * q8) = vq;
            *(float4*)(sk + r * ATQ + 4 * q8) = vk;
            int pr = kperm(r);
            // v positions are permuted-d; svt row index = position (consistent
            // with O staging writing position-major)
            svt[(4 * q8 + 0) * ATV + pr] = vv.x;
            svt[(4 * q8 + 1) * ATV + pr] = vv.y;
            svt[(4 * q8 + 2) * ATV + pr] = vv.z;
            svt[(4 * q8 + 3) * ATV + pr] = vv.w;
        }
        __syncthreads();

        // ---- S = Q K^T ----
        float sacc[8][4];
#pragma unroll
        for (int nt = 0; nt < 8; nt++)
#pragma unroll
            for (int r = 0; r < 4; r++) sacc[nt][r] = 0.f;

        const float* aq = sq + (16 * wid + gp) * ATQ + 2 * tg;
        const float* bk = sk + gp * ATQ + 2 * tg;
#pragma unroll
        for (int g = 0; g < 4; g++) {
            uint32_t a[4];
            float2 av0 = *(const float2*)(aq + 8 * g);
            float2 av1 = *(const float2*)(aq + 8 * ATQ + 8 * g);
            a[0] = __float_as_uint(av0.x);
            a[2] = __float_as_uint(av0.y);
            a[1] = __float_as_uint(av1.x);
            a[3] = __float_as_uint(av1.y);
#pragma unroll
            for (int nt = 0; nt < 8; nt++) {
                uint32_t b[2];
                float2 bv = *(const float2*)(bk + 8 * nt * ATQ + 8 * g);
                b[0] = __float_as_uint(bv.x);
                b[1] = __float_as_uint(bv.y);
                mma_m16n8k8(sacc[nt], a, b);
            }
        }

        // ---- fragment softmax ----
        int r0 = 16 * wid + gp, r1 = r0 + 8;
        int i0 = (r0 < PPp) ? r0 : 0;
        int i1 = (r1 < PPp) ? r1 : 0;
        int ii0 = i0 / 7, ij0 = i0 - ii0 * 7;
        int ii1 = i1 / 7, ij1 = i1 - ii1 * 7;
        const float* sbh = ssb + head * 176;

        float m0 = -1e30f, m1 = -1e30f;
#pragma unroll
        for (int nt = 0; nt < 8; nt++) {
#pragma unroll
            for (int cc = 0; cc < 2; cc++) {
                int j = 8 * nt + 2 * tg + cc;
                if (j < PPp) {
                    int jj1 = j / 7, jj2 = j - (j / 7) * 7;
                    float b0v = sbh[(ii0 - jj1 + 6) * 13 + (ij0 - jj2 + 6)];
                    float b1v = sbh[(ii1 - jj1 + 6) * 13 + (ij1 - jj2 + 6)];
                    sacc[nt][cc]     = sacc[nt][cc] * scale + b0v;
                    sacc[nt][2 + cc] = sacc[nt][2 + cc] * scale + b1v;
                    m0 = fmaxf(m0, sacc[nt][cc]);
                    m1 = fmaxf(m1, sacc[nt][2 + cc]);
                } else {
                    sacc[nt][cc] = -1e30f;
                    sacc[nt][2 + cc] = -1e30f;
                }
            }
        }
        m0 = fmaxf(m0, __shfl_xor_sync(0xFFFFFFFFu, m0, 1));
        m0 = fmaxf(m0, __shfl_xor_sync(0xFFFFFFFFu, m0, 2));
        m1 = fmaxf(m1, __shfl_xor_sync(0xFFFFFFFFu, m1, 1));
        m1 = fmaxf(m1, __shfl_xor_sync(0xFFFFFFFFu, m1, 2));

        float s0 = 0.f, s1 = 0.f;
#pragma unroll
        for (int nt = 0; nt < 8; nt++) {
#pragma unroll
            for (int cc = 0; cc < 2; cc++) {
                float e0 = __expf(sacc[nt][cc] - m0);
                float e1 = __expf(sacc[nt][2 + cc] - m1);
                sacc[nt][cc] = e0;
                sacc[nt][2 + cc] = e1;
                s0 += e0;
                s1 += e1;
            }
        }
        s0 += __shfl_xor_sync(0xFFFFFFFFu, s0, 1);
        s0 += __shfl_xor_sync(0xFFFFFFFFu, s0, 2);
        s1 += __shfl_xor_sync(0xFFFFFFFFu, s1, 1);
        s1 += __shfl_xor_sync(0xFFFFFFFFu, s1, 2);

        // ---- store P (j-permuted, tf32) ----
        {
            float* pr0 = sp + r0 * ATV;
            float* pr1 = sp + r1 * ATV;
#pragma unroll
            for (int nt = 0; nt < 8; nt++) {
#pragma unroll
                for (int cc = 0; cc < 2; cc++) {
                    int j = 8 * nt + 2 * tg + cc;
                    int pj = kperm(j);
                    pr0[pj] = f2tf_f(sacc[nt][cc]);
                    pr1[pj] = f2tf_f(sacc[nt][2 + cc]);
                }
            }
        }
        __syncwarp();

        // ---- O = P V ----
        float oacc[4][4];
#pragma unroll
        for (int nt = 0; nt < 4; nt++)
#pragma unroll
            for (int r = 0; r < 4; r++) oacc[nt][r] = 0.f;

        const float* ap = sp + (16 * wid + gp) * ATV + 2 * tg;
        const float* bv = svt + gp * ATV + 2 * tg;
#pragma unroll
        for (int g = 0; g < 8; g++) {
            uint32_t a[4];
            float2 av0 = *(const float2*)(ap + 8 * g);
            float2 av1 = *(const float2*)(ap + 8 * ATV + 8 * g);
            a[0] = __float_as_uint(av0.x);
            a[2] = __float_as_uint(av0.y);
            a[1] = __float_as_uint(av1.x);
            a[3] = __float_as_uint(av1.y);
#pragma unroll
            for (int nt = 0; nt < 4; nt++) {
                uint32_t b[2];
                float2 bvv = *(const float2*)(bv + 8 * nt * ATV + 8 * g);
                b[0] = __float_as_uint(bvv.x);
                b[1] = __float_as_uint(bvv.y);
                mma_m16n8k8(oacc[nt], a, b);
            }
        }

        // ---- stage O into own sq strip: position-major = already-permuted d ----
        float inv0 = 1.f / s0, inv1 = 1.f / s1;
        if (r0 < PPp) {
            float* st = sq + r0 * ATQ;
#pragma unroll
            for (int nt = 0; nt < 4; nt++) {
                float2 v = make_float2(f2tf_f(oacc[nt][0] * inv0),
                                       f2tf_f(oacc[nt][1] * inv0));
                *(float2*)(st + 8 * nt + 2 * tg) = v;
            }
        }
        if (r1 < PPp) {
            float* st = sq + r1 * ATQ;
#pragma unroll
            for (int nt = 0; nt < 4; nt++) {
                float2 v = make_float2(f2tf_f(oacc[nt][2] * inv1),
                                       f2tf_f(oacc[nt][3] * inv1));
                *(float2*)(st + 8 * nt + 2 * tg) = v;
            }
        }
        __syncthreads();

        // ---- coalesced float4 store ----
        for (int idx = tid; idx < PPp * 8; idx += 128) {
            int r = idx >> 3, q4 = idx & 7;
            float4 v = *(const float4*)(sq + r * ATQ + 4 * q4);
            *(float4*)(attn + (size_t)(base + r) * Cch + head * HDIM + 4 * q4) = v;
        }
    }
}

// ───────────────────────── launch ─────────────────────────
extern "C" void kernel_launch(void* const* d_in, const int* in_sizes, int n_in,
                              void* d_out, int out_size) {
    const float* x       = (const float*)d_in[0];
    const float* w_qkv   = (const float*)d_in[1];
    const float* b_qkv   = (const float*)d_in[2];
    const float* rel_pos = (const float*)d_in[3];
    const float* w_out   = (const float*)d_in[4];
    const float* b_out   = (const float*)d_in[5];
    float* out = (float*)d_out;

    float *p_xw, *p_qkv, *p_attn, *p_out2, *p_wqkv, *p_wout;
    cudaGetSymbolAddress((void**)&p_xw, g_xw);
    cudaGetSymbolAddress((void**)&p_qkv, g_qkv);
    cudaGetSymbolAddress((void**)&p_attn, g_attn);
    cudaGetSymbolAddress((void**)&p_out2, g_out2);
    cudaGetSymbolAddress((void**)&p_wqkv, g_wqkv);
    cudaGetSymbolAddress((void**)&p_wout, g_wout);

    cudaFuncSetAttribute(k_gemm_mma<0>, cudaFuncAttributeMaxDynamicSharedMemorySize, GEMM_SMEM);
    cudaFuncSetAttribute(k_gemm_mma<1>, cudaFuncAttributeMaxDynamicSharedMemorySize, GEMM_SMEM);

    k_round<<<(576 * 192 + 255) / 256, 256>>>(w_qkv, p_wqkv, 576 * 192);
    k_round<<<(192 * 192 + 255) / 256, 256>>>(w_out, p_wout, 192 * 192);

    dim3 tb(32, 8);
    dim3 tg(HWSZ / 32, Cch / 32, Bsz);
    k_gather<<<tg, tb>>>(x, p_xw);
    k_gemm_mma<1><<<dim3(576 / GBN, Mrows / GBM), 256, GEMM_SMEM>>>(p_xw, p_wqkv, b_qkv, p_qkv, 576);
    k_attn_mma<<<592, 128>>>(p_qkv, p_attn, rel_pos);
    k_gemm_mma<0><<<dim3(192 / GBN, Mrows / GBM), 256, GEMM_SMEM>>>(p_attn, p_wout, b_out, p_out2, 192);
    k_scatter<<<tg, tb>>>(p_out2, out);
}

// round 15
// speedup vs baseline: 1.5436x; 1.5436x over previous
#include <cuda_runtime.h>
#include <cuda_fp16.h>
#include <cstdint>

#define Bsz   8
#define Cch   192
#define Himg  224
#define Wimg  224
#define Pw    7
#define NHEAD 6
#define HDIM  32
#define WGRID 32
#define NWIN  1024
#define PPp   49
#define Mrows 401408
#define HWSZ  50176
#define NPROB (Bsz * NWIN * NHEAD)

static __device__ __half g_xw[(size_t)Mrows * Cch];
static __device__ __half g_qkv[(size_t)Mrows * 3 * Cch];
static __device__ __half g_attn[(size_t)Mrows * Cch];
static __device__ float  g_out2[(size_t)Mrows * Cch];
static __device__ __half g_wqkv[576 * 192];
static __device__ __half g_wout[192 * 192];

// pair-permutation within 8-pair (16-element) groups: q = 2*(p&3) + (p>>2)
__device__ __forceinline__ int pperm(int p) { return ((p & 3) << 1) | (p >> 2); }
// half-element permuted position within 16-channel groups
__device__ __forceinline__ int hpos(int c) {
    int pg = (c >> 1) & 7, s = c & 1;
    return (c & ~15) | (pperm(pg) << 1) | s;
}

__device__ __forceinline__ void mma_f16(float* c, uint32_t a0, uint32_t a1,
                                        uint32_t a2, uint32_t a3,
                                        uint32_t b0, uint32_t b1) {
    asm volatile(
        "mma.sync.aligned.m16n8k16.row.col.f32.f16.f16.f32 "
        "{%0,%1,%2,%3}, {%4,%5,%6,%7}, {%8,%9}, {%0,%1,%2,%3};"
        : "+f"(c[0]), "+f"(c[1]), "+f"(c[2]), "+f"(c[3])
        : "r"(a0), "r"(a1), "r"(a2), "r"(a3), "r"(b0), "r"(b1));
}
__device__ __forceinline__ void cp16(uint32_t dst, const void* src) {
    asm volatile("cp.async.cg.shared.global [%0], [%1], 16;" :: "r"(dst), "l"(src));
}
#define CP_COMMIT() asm volatile("cp.async.commit_group;" ::: "memory")
#define CP_WAIT(n)  asm volatile("cp.async.wait_group %0;" :: "n"(n) : "memory")

__global__ void k_round(const float* __restrict__ w, __half* __restrict__ o, int n) {
    int i = blockIdx.x * 256 + threadIdx.x;
    if (i < n) {
        int row = i / 192, k = i - row * 192;
        o[row * 192 + hpos(k)] = __float2half_rn(w[i]);
    }
}

// ───────────────────────── transposes ─────────────────────────
__device__ __forceinline__ int m_of(int b, int hw) {
    int h = hw / Wimg;
    int w = hw - h * Wimg;
    int wi = h / Pw, pi = h - wi * Pw;
    int wj = w / Pw, pj = w - wj * Pw;
    return ((b * WGRID + wi) * WGRID + wj) * PPp + pi * Pw + pj;
}

__global__ void k_gather(const float* __restrict__ x, __half* __restrict__ xw) {
    __shared__ float tile[32][33];
    int hw0 = blockIdx.x << 5, c0 = blockIdx.y << 5, b = blockIdx.z;
    int tx = threadIdx.x, ty = threadIdx.y;
    const float* xb = x + (size_t)b * Cch * HWSZ;
#pragma unroll
    for (int it = 0; it < 4; it++) {
        int c = c0 + ty + it * 8;
        tile[ty + it * 8][tx] = xb[(size_t)c * HWSZ + hw0 + tx];
    }
    __syncthreads();
    int cp = hpos(c0 + tx);
#pragma unroll
    for (int it = 0; it < 4; it++) {
        int hw = hw0 + ty + it * 8;
        int m = m_of(b, hw);
        xw[(size_t)m * Cch + cp] = __float2half_rn(tile[tx][ty + it * 8]);
    }
}

__global__ void k_scatter(const float* __restrict__ out2, float* __restrict__ out) {
    __shared__ float tile[32][33];
    int hw0 = blockIdx.x << 5, c0 = blockIdx.y << 5, b = blockIdx.z;
    int tx = threadIdx.x, ty = threadIdx.y;
#pragma unroll
    for (int it = 0; it < 4; it++) {
        int hw = hw0 + ty + it * 8;
        int m = m_of(b, hw);
        tile[ty + it * 8][tx] = out2[(size_t)m * Cch + c0 + tx];
    }
    __syncthreads();
    float* ob = out + (size_t)b * Cch * HWSZ;
#pragma unroll
    for (int it = 0; it < 4; it++) {
        int c = c0 + ty + it * 8;
        ob[(size_t)c * HWSZ + hw0 + tx] = tile[tx][ty + it * 8];
    }
}

// ───── FP16 GEMM: streaming double-buffer, m16n8k16, paired LDS.64 ─────
// BM=128, BN=64, BK=32 half (2 k16-groups), stride 24 uint/row (phase-conflict-free).
#define GBM 128
#define GBN 64
#define KTOT 192
#define KTILES 6
#define STRH 24
#define A_U (GBM * STRH)          // 3072 uint
#define B_U (GBN * STRH)          // 1536 uint
#define GEMM_SMEM (2 * (A_U + B_U) * 4)   // 36864 B

template <int OUTF>
__global__ void __launch_bounds__(256, 3)
k_gemm_f16(const __half* __restrict__ A, const __half* __restrict__ Wt,
           const float* __restrict__ bias, void* __restrict__ Cv, int Ntot) {
    extern __shared__ uint32_t smu[];

    int tid = threadIdx.x;
    int wid = tid >> 5, lane = tid & 31;
    int gp = lane >> 2, tg = lane & 3;
    int wm = wid & 3, wn = wid >> 2;
    size_t bm = (size_t)blockIdx.y * GBM;
    int bn = blockIdx.x * GBN;

    uint32_t smb = (uint32_t)__cvta_generic_to_shared(smu);
    const uint32_t STG_B = (A_U + B_U) * 4;

    int ar = tid >> 1;                       // A loader rows (2 cp16 each)
    int br = tid >> 2, bq = tid & 3;

#define LOAD_T(t, so) do {                                                    \
        int _k0 = (t) * 32;                                                   \
        _Pragma("unroll")                                                     \
        for (int u = 0; u < 2; u++) {                                         \
            int _idx = tid + 256 * u;                                         \
            int _r = _idx >> 2, _q = _idx & 3;                                \
            cp16(smb + (so) + (_r * STRH + _q * 4) * 4,                       \
                 A + (bm + _r) * KTOT + _k0 + _q * 8);                        \
        }                                                                     \
        cp16(smb + (so) + (A_U + br * STRH + bq * 4) * 4,                     \
             Wt + (size_t)(bn + br) * KTOT + _k0 + bq * 8);                   \
    } while (0)

    (void)ar;
    LOAD_T(0, 0);
    CP_COMMIT();

    float acc[2][4][4];
#pragma unroll
    for (int mt = 0; mt < 2; mt++)
#pragma unroll
        for (int nt = 0; nt < 4; nt++)
#pragma unroll
            for (int r = 0; r < 4; r++) acc[mt][nt][r] = 0.f;

    const uint32_t arow = (wm * 32 + gp) * STRH + 2 * tg;
    const uint32_t brow = A_U + (wn * 32 + gp) * STRH + 2 * tg;

#pragma unroll 1
    for (int t = 0; t < KTILES; t++) {
        if (t + 1 < KTILES) {
            LOAD_T(t + 1, ((t + 1) & 1) * STG_B);
            CP_COMMIT();
            CP_WAIT(1);
        } else {
            CP_WAIT(0);
        }
        __syncthreads();

        const uint32_t* sm = smu + (t & 1) * (STG_B / 4);
#pragma unroll
        for (int g = 0; g < 2; g++) {
            uint32_t a[2][4], b[4][2];
#pragma unroll
            for (int mt = 0; mt < 2; mt++) {
                uint2 v0 = *(const uint2*)(sm + arow + mt * 16 * STRH + g * 8);
                uint2 v1 = *(const uint2*)(sm + arow + mt * 16 * STRH + 8 * STRH + g * 8);
                a[mt][0] = v0.x; a[mt][2] = v0.y;
                a[mt][1] = v1.x; a[mt][3] = v1.y;
            }
#pragma unroll
            for (int nt = 0; nt < 4; nt++) {
                uint2 w = *(const uint2*)(sm + brow + nt * 8 * STRH + g * 8);
                b[nt][0] = w.x; b[nt][1] = w.y;
            }
#pragma unroll
            for (int mt = 0; mt < 2; mt++)
#pragma unroll
                for (int nt = 0; nt < 4; nt++)
                    mma_f16(acc[mt][nt], a[mt][0], a[mt][1], a[mt][2], a[mt][3],
                            b[nt][0], b[nt][1]);
        }
        __syncthreads();
    }
#undef LOAD_T

#pragma unroll
    for (int mt = 0; mt < 2; mt++) {
        int row = (int)bm + wm * 32 + mt * 16 + gp;
#pragma unroll
        for (int nt = 0; nt < 4; nt++) {
            int col = bn + wn * 32 + nt * 8 + tg * 2;
            float b0 = bias[col], b1 = bias[col + 1];
            if (OUTF) {
                float* Cf = (float*)Cv;
                *(float2*)(Cf + (size_t)row * Ntot + col) =
                    make_float2(acc[mt][nt][0] + b0, acc[mt][nt][1] + b1);
                *(float2*)(Cf + (size_t)(row + 8) * Ntot + col) =
                    make_float2(acc[mt][nt][2] + b0, acc[mt][nt][3] + b1);
            } else {
                __half* Ch = (__half*)Cv;
                __half2 h0 = __floats2half2_rn(acc[mt][nt][0] + b0, acc[mt][nt][1] + b1);
                __half2 h1 = __floats2half2_rn(acc[mt][nt][2] + b0, acc[mt][nt][3] + b1);
                *(__half2*)(Ch + (size_t)row * Ntot + col) = h0;
                *(__half2*)(Ch + (size_t)(row + 8) * Ntot + col) = h1;
            }
        }
    }
}

// ───── attention: persistent fp16 tensor-core (m16n8k16) ─────
#define SQ_STR 24     // uint per row (16 data + pad)
#define SV_STR 40     // uint per row (32 data + pad)
#define SP_STR 40

__global__ void __launch_bounds__(128)
k_attn_f16(const __half* __restrict__ qkv, __half* __restrict__ attn,
           const float* __restrict__ rel_pos) {
    __shared__ uint32_t sq[64 * SQ_STR];
    __shared__ uint32_t sk[64 * SQ_STR];
    __shared__ uint32_t svt[32 * SV_STR];
    __shared__ uint32_t sp[64 * SP_STR];
    __shared__ float ssb[NHEAD * 176];

    int tid = threadIdx.x;
    int wid = tid >> 5, lane = tid & 31;
    int gp = lane >> 2, tg = lane & 3;
    const float scale = 0.17677669529663687f;

    // one-time init: zero pads + bias
    for (int i = tid; i < 15 * SQ_STR; i += 128) {
        sq[49 * SQ_STR + i] = 0u;
        sk[49 * SQ_STR + i] = 0u;
    }
    for (int i = tid; i < 32 * SV_STR; i += 128) svt[i] = 0u;
    for (int i = tid; i < NHEAD * 169; i += 128) {
        int h = i / 169, e = i - h * 169;
        ssb[h * 176 + e] = rel_pos[i];
    }

#pragma unroll 1
    for (int blk = blockIdx.x; blk < NPROB; blk += gridDim.x) {
        int head = blk % NHEAD;
        int win = blk / NHEAD;
        int base = win * PPp;
        const size_t rowb = (size_t)base * 576 + head * HDIM;   // half units

        __syncthreads();

        // stage Q/K (pair-permuted d) and V^T (d rows, pair-permuted j halves)
        for (int idx = tid; idx < PPp * 4; idx += 128) {
            int r = idx >> 2, q4 = idx & 3;           // q4: which float4 (8 halves)
            const __half* rowp = qkv + rowb + (size_t)r * 576;
            uint4 vq = *((const uint4*)rowp + q4);
            uint4 vk = *((const uint4*)(rowp + 192) + q4);
            uint4 vv = *((const uint4*)(rowp + 384) + q4);
            int grp = q4 >> 1;
            int off0 = grp * 8 + ((q4 & 1) ? 1 : 0);  // pperm: even q4 -> 0,2,4,6; odd -> 1,3,5,7
            uint32_t* sqr = sq + r * SQ_STR;
            uint32_t* skr = sk + r * SQ_STR;
            uint32_t qa[4] = {vq.x, vq.y, vq.z, vq.w};
            uint32_t ka[4] = {vk.x, vk.y, vk.z, vk.w};
            uint32_t va[4] = {vv.x, vv.y, vv.z, vv.w};
#pragma unroll
            for (int i2 = 0; i2 < 4; i2++) {
                sqr[off0 + 2 * i2] = qa[i2];
                skr[off0 + 2 * i2] = ka[i2];
            }
            // V: halves d = 8*q4 + 2*i2 (+1); j position = (r>>4)*16 + pperm((r>>1)&7)*2 + (r&1)
            int jp = ((r >> 4) << 4) + (pperm((r >> 1) & 7) << 1) + (r & 1);
#pragma unroll
            for (int i2 = 0; i2 < 4; i2++) {
                int d0 = 8 * q4 + 2 * i2;
                __half2 hv = *(__half2*)&va[i2];
                ((__half*)(svt + d0 * SV_STR))[jp] = __low2half(hv);
                ((__half*)(svt + (d0 + 1) * SV_STR))[jp] = __high2half(hv);
            }
        }
        __syncthreads();

        // ---- S = Q K^T : warp strip rows 16*wid..+15, 8 n-tiles, 2 k16-groups ----
        float sacc[8][4];
#pragma unroll
        for (int nt = 0; nt < 8; nt++)
#pragma unroll
            for (int r = 0; r < 4; r++) sacc[nt][r] = 0.f;

        const uint32_t aqb = (16 * wid + gp) * SQ_STR + 2 * tg;
#pragma unroll
        for (int g = 0; g < 2; g++) {
            uint2 v0 = *(const uint2*)(sq + aqb + g * 8);
            uint2 v1 = *(const uint2*)(sq + aqb + 8 * SQ_STR + g * 8);
#pragma unroll
            for (int nt = 0; nt < 8; nt++) {
                uint2 w = *(const uint2*)(sk + (8 * nt + gp) * SQ_STR + 2 * tg + g * 8);
                mma_f16(sacc[nt], v0.x, v1.x, v0.y, v1.y, w.x, w.y);
            }
        }

        // ---- fragment softmax ----
        int r0 = 16 * wid + gp, r1 = r0 + 8;
        int i0 = (r0 < PPp) ? r0 : 0;
        int i1 = (r1 < PPp) ? r1 : 0;
        int ii0 = i0 / 7, ij0 = i0 - ii0 * 7;
        int ii1 = i1 / 7, ij1 = i1 - ii1 * 7;
        const float* sbh = ssb + head * 176;

        float m0 = -1e30f, m1 = -1e30f;
#pragma unroll
        for (int nt = 0; nt < 8; nt++) {
#pragma unroll
            for (int cc = 0; cc < 2; cc++) {
                int j = 8 * nt + 2 * tg + cc;
                if (j < PPp) {
                    int jj1 = j / 7, jj2 = j - (j / 7) * 7;
                    float b0v = sbh[(ii0 - jj1 + 6) * 13 + (ij0 - jj2 + 6)];
                    float b1v = sbh[(ii1 - jj1 + 6) * 13 + (ij1 - jj2 + 6)];
                    sacc[nt][cc]     = sacc[nt][cc] * scale + b0v;
                    sacc[nt][2 + cc] = sacc[nt][2 + cc] * scale + b1v;
                    m0 = fmaxf(m0, sacc[nt][cc]);
                    m1 = fmaxf(m1, sacc[nt][2 + cc]);
                } else {
                    sacc[nt][cc] = -1e30f;
                    sacc[nt][2 + cc] = -1e30f;
                }
            }
        }
        m0 = fmaxf(m0, __shfl_xor_sync(0xFFFFFFFFu, m0, 1));
        m0 = fmaxf(m0, __shfl_xor_sync(0xFFFFFFFFu, m0, 2));
        m1 = fmaxf(m1, __shfl_xor_sync(0xFFFFFFFFu, m1, 1));
        m1 = fmaxf(m1, __shfl_xor_sync(0xFFFFFFFFu, m1, 2));

        float s0 = 0.f, s1 = 0.f;
#pragma unroll
        for (int nt = 0; nt < 8; nt++) {
#pragma unroll
            for (int cc = 0; cc < 2; cc++) {
                float e0 = __expf(sacc[nt][cc] - m0);
                float e1 = __expf(sacc[nt][2 + cc] - m1);
                sacc[nt][cc] = e0;
                sacc[nt][2 + cc] = e1;
                s0 += e0;
                s1 += e1;
            }
        }
        s0 += __shfl_xor_sync(0xFFFFFFFFu, s0, 1);
        s0 += __shfl_xor_sync(0xFFFFFFFFu, s0, 2);
        s1 += __shfl_xor_sync(0xFFFFFFFFu, s1, 1);
        s1 += __shfl_xor_sync(0xFFFFFFFFu, s1, 2);

        // ---- store P as half2 (j pairs, pair-permuted) ----
        {
            uint32_t* pr0 = sp + r0 * SP_STR;
            uint32_t* pr1 = sp + r1 * SP_STR;
#pragma unroll
            for (int nt = 0; nt < 8; nt++) {
                int p = 4 * nt + tg;                    // global pair index 0..31
                int pos = ((p >> 3) << 3) + pperm(p & 7);
                __half2 h0 = __floats2half2_rn(sacc[nt][0], sacc[nt][1]);
                __half2 h1 = __floats2half2_rn(sacc[nt][2], sacc[nt][3]);
                pr0[pos] = *(uint32_t*)&h0;
                pr1[pos] = *(uint32_t*)&h1;
            }
        }
        __syncwarp();

        // ---- O = P V : 4 n-tiles (32 d), 4 k16-groups (64 j) ----
        float oacc[4][4];
#pragma unroll
        for (int nt = 0; nt < 4; nt++)
#pragma unroll
            for (int r = 0; r < 4; r++) oacc[nt][r] = 0.f;

        const uint32_t apb = (16 * wid + gp) * SP_STR + 2 * tg;
#pragma unroll
        for (int g = 0; g < 4; g++) {
            uint2 v0 = *(const uint2*)(sp + apb + g * 8);
            uint2 v1 = *(const uint2*)(sp + apb + 8 * SP_STR + g * 8);
#pragma unroll
            for (int nt = 0; nt < 4; nt++) {
                uint2 w = *(const uint2*)(svt + (8 * nt + gp) * SV_STR + 2 * tg + g * 8);
                mma_f16(oacc[nt], v0.x, v1.x, v0.y, v1.y, w.x, w.y);
            }
        }

        // ---- stage O into sq rows (pair-permuted d for out-GEMM), coalesced out ----
        float inv0 = 1.f / s0, inv1 = 1.f / s1;
        if (r0 < PPp) {
            uint32_t* st = sq + r0 * SQ_STR;
#pragma unroll
            for (int nt = 0; nt < 4; nt++) {
                int p = 4 * nt + tg;                    // d-pair 0..15
                int pos = ((p >> 3) << 3) + pperm(p & 7);
                __half2 h = __floats2half2_rn(oacc[nt][0] * inv0, oacc[nt][1] * inv0);
                st[pos] = *(uint32_t*)&h;
            }
        }
        if (r1 < PPp) {
            uint32_t* st = sq + r1 * SQ_STR;
#pragma unroll
            for (int nt = 0; nt < 4; nt++) {
                int p = 4 * nt + tg;
                int pos = ((p >> 3) << 3) + pperm(p & 7);
                __half2 h = __floats2half2_rn(oacc[nt][2] * inv1, oacc[nt][3] * inv1);
                st[pos] = *(uint32_t*)&h;
            }
        }
        __syncthreads();

        for (int idx = tid; idx < PPp * 4; idx += 128) {
            int r = idx >> 2, q4 = idx & 3;
            uint4 v = *(const uint4*)(sq + r * SQ_STR + 4 * q4);
            *(uint4*)(attn + (size_t)(base + r) * Cch + head * HDIM + 8 * q4) = v;
        }
    }
}

// ───────────────────────── launch ─────────────────────────
extern "C" void kernel_launch(void* const* d_in, const int* in_sizes, int n_in,
                              void* d_out, int out_size) {
    const float* x       = (const float*)d_in[0];
    const float* w_qkv   = (const float*)d_in[1];
    const float* b_qkv   = (const float*)d_in[2];
    const float* rel_pos = (const float*)d_in[3];
    const float* w_out   = (const float*)d_in[4];
    const float* b_out   = (const float*)d_in[5];
    float* out = (float*)d_out;

    __half *p_xw, *p_qkv, *p_attn, *p_wqkv, *p_wout;
    float *p_out2;
    cudaGetSymbolAddress((void**)&p_xw, g_xw);
    cudaGetSymbolAddress((void**)&p_qkv, g_qkv);
    cudaGetSymbolAddress((void**)&p_attn, g_attn);
    cudaGetSymbolAddress((void**)&p_out2, g_out2);
    cudaGetSymbolAddress((void**)&p_wqkv, g_wqkv);
    cudaGetSymbolAddress((void**)&p_wout, g_wout);

    cudaFuncSetAttribute(k_gemm_f16<0>, cudaFuncAttributeMaxDynamicSharedMemorySize, GEMM_SMEM);
    cudaFuncSetAttribute(k_gemm_f16<1>, cudaFuncAttributeMaxDynamicSharedMemorySize, GEMM_SMEM);

    k_round<<<(576 * 192 + 255) / 256, 256>>>(w_qkv, p_wqkv, 576 * 192);
    k_round<<<(192 * 192 + 255) / 256, 256>>>(w_out, p_wout, 192 * 192);

    dim3 tb(32, 8);
    dim3 tg(HWSZ / 32, Cch / 32, Bsz);
    k_gather<<<tg, tb>>>(x, p_xw);
    k_gemm_f16<0><<<dim3(576 / GBN, Mrows / GBM), 256, GEMM_SMEM>>>(p_xw, p_wqkv, b_qkv, p_qkv, 576);
    k_attn_f16<<<592, 128>>>(p_qkv, p_attn, rel_pos);
    k_gemm_f16<1><<<dim3(192 / GBN, Mrows / GBM), 256, GEMM_SMEM>>>(p_attn, p_wout, b_out, p_out2, 192);
    k_scatter<<<tg, tb>>>(p_out2, out);
}

// round 16
// speedup vs baseline: 1.5961x; 1.0340x over previous
#include <cuda_runtime.h>
#include <cuda_fp16.h>
#include <cstdint>

#define Bsz   8
#define Cch   192
#define Himg  224
#define Wimg  224
#define Pw    7
#define NHEAD 6
#define HDIM  32
#define WGRID 32
#define NWIN  1024
#define PPp   49
#define Mrows 401408
#define HWSZ  50176
#define NPROB (Bsz * NWIN * NHEAD)

static __device__ __half g_xw[(size_t)Mrows * Cch];
static __device__ __half g_qkv[(size_t)Mrows * 3 * Cch];
static __device__ __half g_attn[(size_t)Mrows * Cch];
static __device__ __half g_out2[(size_t)Mrows * Cch];
static __device__ __half g_wqkv[576 * 192];
static __device__ __half g_wout[192 * 192];

// pair-permutation within 8-pair (16-element) groups
__device__ __forceinline__ int pperm(int p) { return ((p & 3) << 1) | (p >> 2); }
__device__ __forceinline__ int hpos(int c) {
    int pg = (c >> 1) & 7, s = c & 1;
    return (c & ~15) | (pperm(pg) << 1) | s;
}

__device__ __forceinline__ void mma_f16(float* c, uint32_t a0, uint32_t a1,
                                        uint32_t a2, uint32_t a3,
                                        uint32_t b0, uint32_t b1) {
    asm volatile(
        "mma.sync.aligned.m16n8k16.row.col.f32.f16.f16.f32 "
        "{%0,%1,%2,%3}, {%4,%5,%6,%7}, {%8,%9}, {%0,%1,%2,%3};"
        : "+f"(c[0]), "+f"(c[1]), "+f"(c[2]), "+f"(c[3])
        : "r"(a0), "r"(a1), "r"(a2), "r"(a3), "r"(b0), "r"(b1));
}
__device__ __forceinline__ void cp16(uint32_t dst, const void* src) {
    asm volatile("cp.async.cg.shared.global [%0], [%1], 16;" :: "r"(dst), "l"(src));
}
#define CP_COMMIT() asm volatile("cp.async.commit_group;" ::: "memory")
#define CP_WAIT(n)  asm volatile("cp.async.wait_group %0;" :: "n"(n) : "memory")

__global__ void k_round(const float* __restrict__ w, __half* __restrict__ o, int n) {
    int i = blockIdx.x * 256 + threadIdx.x;
    if (i < n) {
        int row = i / 192, k = i - row * 192;
        o[row * 192 + hpos(k)] = __float2half_rn(w[i]);
    }
}

// ───────────────────────── transposes ─────────────────────────
__device__ __forceinline__ int m_of(int b, int hw) {
    int h = hw / Wimg;
    int w = hw - h * Wimg;
    int wi = h / Pw, pi = h - wi * Pw;
    int wj = w / Pw, pj = w - wj * Pw;
    return ((b * WGRID + wi) * WGRID + wj) * PPp + pi * Pw + pj;
}

__global__ void k_gather(const float* __restrict__ x, __half* __restrict__ xw) {
    __shared__ float tile[32][33];
    int hw0 = blockIdx.x << 5, c0 = blockIdx.y << 5, b = blockIdx.z;
    int tx = threadIdx.x, ty = threadIdx.y;
    const float* xb = x + (size_t)b * Cch * HWSZ;
#pragma unroll
    for (int it = 0; it < 4; it++) {
        int c = c0 + ty + it * 8;
        tile[ty + it * 8][tx] = xb[(size_t)c * HWSZ + hw0 + tx];
    }
    __syncthreads();
    int cp = hpos(c0 + tx);
#pragma unroll
    for (int it = 0; it < 4; it++) {
        int hw = hw0 + ty + it * 8;
        int m = m_of(b, hw);
        xw[(size_t)m * Cch + cp] = __float2half_rn(tile[tx][ty + it * 8]);
    }
}

__global__ void k_scatter(const __half* __restrict__ out2, float* __restrict__ out) {
    __shared__ float tile[32][33];
    int hw0 = blockIdx.x << 5, c0 = blockIdx.y << 5, b = blockIdx.z;
    int tx = threadIdx.x, ty = threadIdx.y;
#pragma unroll
    for (int it = 0; it < 4; it++) {
        int hw = hw0 + ty + it * 8;
        int m = m_of(b, hw);
        tile[ty + it * 8][tx] = __half2float(out2[(size_t)m * Cch + c0 + tx]);
    }
    __syncthreads();
    float* ob = out + (size_t)b * Cch * HWSZ;
#pragma unroll
    for (int it = 0; it < 4; it++) {
        int c = c0 + ty + it * 8;
        ob[(size_t)c * HWSZ + hw0 + tx] = tile[tx][ty + it * 8];
    }
}

// ───── FP16 GEMM: BM=128 BN=96 BK=32, m16n8k16, warptile 32x48 ─────
#define GBM 128
#define GBN 96
#define KTOT 192
#define KTILES 6
#define STRH 24
#define A_U (GBM * STRH)          // 3072 uint
#define B_U (GBN * STRH)          // 2304 uint
#define GEMM_SMEM (2 * (A_U + B_U) * 4)   // 43008 B

__global__ void __launch_bounds__(256, 3)
k_gemm_f16(const __half* __restrict__ A, const __half* __restrict__ Wt,
           const float* __restrict__ bias, __half* __restrict__ C, int Ntot) {
    extern __shared__ uint32_t smu[];

    int tid = threadIdx.x;
    int wid = tid >> 5, lane = tid & 31;
    int gp = lane >> 2, tg = lane & 3;
    int wm = wid & 3, wn = wid >> 2;          // 4(M) x 2(N)
    size_t bm = (size_t)blockIdx.y * GBM;
    int bn = blockIdx.x * GBN;

    uint32_t smb = (uint32_t)__cvta_generic_to_shared(smu);
    const uint32_t STG_B = (A_U + B_U) * 4;

#define LOAD_T(t, so) do {                                                    \
        int _k0 = (t) * 32;                                                   \
        _Pragma("unroll")                                                     \
        for (int u = 0; u < 2; u++) {                                         \
            int _idx = tid + 256 * u;                                         \
            int _r = _idx >> 2, _q = _idx & 3;                                \
            cp16(smb + (so) + (_r * STRH + _q * 4) * 4,                       \
                 A + (bm + _r) * KTOT + _k0 + _q * 8);                        \
        }                                                                     \
        _Pragma("unroll")                                                     \
        for (int u = 0; u < 2; u++) {                                         \
            int _idx = tid + 256 * u;                                         \
            if (_idx < GBN * 4) {                                             \
                int _r = _idx >> 2, _q = _idx & 3;                            \
                cp16(smb + (so) + (A_U + _r * STRH + _q * 4) * 4,             \
                     Wt + (size_t)(bn + _r) * KTOT + _k0 + _q * 8);           \
            }                                                                 \
        }                                                                     \
    } while (0)

    LOAD_T(0, 0);
    CP_COMMIT();

    float acc[2][6][4];
#pragma unroll
    for (int mt = 0; mt < 2; mt++)
#pragma unroll
        for (int nt = 0; nt < 6; nt++)
#pragma unroll
            for (int r = 0; r < 4; r++) acc[mt][nt][r] = 0.f;

    const uint32_t arow = (wm * 32 + gp) * STRH + 2 * tg;
    const uint32_t brow = A_U + (wn * 48 + gp) * STRH + 2 * tg;

#pragma unroll 1
    for (int t = 0; t < KTILES; t++) {
        if (t + 1 < KTILES) {
            LOAD_T(t + 1, ((t + 1) & 1) * STG_B);
            CP_COMMIT();
            CP_WAIT(1);
        } else {
            CP_WAIT(0);
        }
        __syncthreads();

        const uint32_t* sm = smu + (t & 1) * (STG_B / 4);
#pragma unroll
        for (int g = 0; g < 2; g++) {
            uint32_t a[2][4], b[6][2];
#pragma unroll
            for (int mt = 0; mt < 2; mt++) {
                uint2 v0 = *(const uint2*)(sm + arow + mt * 16 * STRH + g * 8);
                uint2 v1 = *(const uint2*)(sm + arow + mt * 16 * STRH + 8 * STRH + g * 8);
                a[mt][0] = v0.x; a[mt][2] = v0.y;
                a[mt][1] = v1.x; a[mt][3] = v1.y;
            }
#pragma unroll
            for (int nt = 0; nt < 6; nt++) {
                uint2 w = *(const uint2*)(sm + brow + nt * 8 * STRH + g * 8);
                b[nt][0] = w.x; b[nt][1] = w.y;
            }
#pragma unroll
            for (int mt = 0; mt < 2; mt++)
#pragma unroll
                for (int nt = 0; nt < 6; nt++)
                    mma_f16(acc[mt][nt], a[mt][0], a[mt][1], a[mt][2], a[mt][3],
                            b[nt][0], b[nt][1]);
        }
        __syncthreads();
    }
#undef LOAD_T

#pragma unroll
    for (int mt = 0; mt < 2; mt++) {
        int row = (int)bm + wm * 32 + mt * 16 + gp;
#pragma unroll
        for (int nt = 0; nt < 6; nt++) {
            int col = bn + wn * 48 + nt * 8 + tg * 2;
            float b0 = bias[col], b1 = bias[col + 1];
            __half2 h0 = __floats2half2_rn(acc[mt][nt][0] + b0, acc[mt][nt][1] + b1);
            __half2 h1 = __floats2half2_rn(acc[mt][nt][2] + b0, acc[mt][nt][3] + b1);
            *(__half2*)(C + (size_t)row * Ntot + col) = h0;
            *(__half2*)(C + (size_t)(row + 8) * Ntot + col) = h1;
        }
    }
}

// ───── attention: persistent fp16 tensor-core (m16n8k16) ─────
#define SQ_STR 24
#define SV_STR 40
#define SP_STR 40

__global__ void __launch_bounds__(128)
k_attn_f16(const __half* __restrict__ qkv, __half* __restrict__ attn,
           const float* __restrict__ rel_pos) {
    __shared__ uint32_t sq[64 * SQ_STR];
    __shared__ uint32_t sk[64 * SQ_STR];
    __shared__ uint32_t svt[32 * SV_STR];
    __shared__ uint32_t sp[64 * SP_STR];
    __shared__ float ssb[NHEAD * 176];

    int tid = threadIdx.x;
    int wid = tid >> 5, lane = tid & 31;
    int gp = lane >> 2, tg = lane & 3;
    const float scale = 0.17677669529663687f;

    for (int i = tid; i < 15 * SQ_STR; i += 128) {
        sq[49 * SQ_STR + i] = 0u;
        sk[49 * SQ_STR + i] = 0u;
    }
    for (int i = tid; i < 32 * SV_STR; i += 128) svt[i] = 0u;
    for (int i = tid; i < NHEAD * 169; i += 128) {
        int h = i / 169, e = i - h * 169;
        ssb[h * 176 + e] = rel_pos[i];
    }

#pragma unroll 1
    for (int blk = blockIdx.x; blk < NPROB; blk += gridDim.x) {
        int head = blk % NHEAD;
        int win = blk / NHEAD;
        int base = win * PPp;
        const size_t rowb = (size_t)base * 576 + head * HDIM;

        __syncthreads();

        for (int idx = tid; idx < PPp * 4; idx += 128) {
            int r = idx >> 2, q4 = idx & 3;
            const __half* rowp = qkv + rowb + (size_t)r * 576;
            uint4 vq = *((const uint4*)rowp + q4);
            uint4 vk = *((const uint4*)(rowp + 192) + q4);
            uint4 vv = *((const uint4*)(rowp + 384) + q4);
            int grp = q4 >> 1;
            int off0 = grp * 8 + ((q4 & 1) ? 1 : 0);
            uint32_t* sqr = sq + r * SQ_STR;
            uint32_t* skr = sk + r * SQ_STR;
            uint32_t qa[4] = {vq.x, vq.y, vq.z, vq.w};
            uint32_t ka[4] = {vk.x, vk.y, vk.z, vk.w};
            uint32_t va[4] = {vv.x, vv.y, vv.z, vv.w};
#pragma unroll
            for (int i2 = 0; i2 < 4; i2++) {
                sqr[off0 + 2 * i2] = qa[i2];
                skr[off0 + 2 * i2] = ka[i2];
            }
            int jp = ((r >> 4) << 4) + (pperm((r >> 1) & 7) << 1) + (r & 1);
#pragma unroll
            for (int i2 = 0; i2 < 4; i2++) {
                int d0 = 8 * q4 + 2 * i2;
                __half2 hv = *(__half2*)&va[i2];
                ((__half*)(svt + d0 * SV_STR))[jp] = __low2half(hv);
                ((__half*)(svt + (d0 + 1) * SV_STR))[jp] = __high2half(hv);
            }
        }
        __syncthreads();

        float sacc[8][4];
#pragma unroll
        for (int nt = 0; nt < 8; nt++)
#pragma unroll
            for (int r = 0; r < 4; r++) sacc[nt][r] = 0.f;

        const uint32_t aqb = (16 * wid + gp) * SQ_STR + 2 * tg;
#pragma unroll
        for (int g = 0; g < 2; g++) {
            uint2 v0 = *(const uint2*)(sq + aqb + g * 8);
            uint2 v1 = *(const uint2*)(sq + aqb + 8 * SQ_STR + g * 8);
#pragma unroll
            for (int nt = 0; nt < 8; nt++) {
                uint2 w = *(const uint2*)(sk + (8 * nt + gp) * SQ_STR + 2 * tg + g * 8);
                mma_f16(sacc[nt], v0.x, v1.x, v0.y, v1.y, w.x, w.y);
            }
        }

        int r0 = 16 * wid + gp, r1 = r0 + 8;
        int i0 = (r0 < PPp) ? r0 : 0;
        int i1 = (r1 < PPp) ? r1 : 0;
        int ii0 = i0 / 7, ij0 = i0 - ii0 * 7;
        int ii1 = i1 / 7, ij1 = i1 - ii1 * 7;
        const float* sbh = ssb + head * 176;

        float m0 = -1e30f, m1 = -1e30f;
#pragma unroll
        for (int nt = 0; nt < 8; nt++) {
#pragma unroll
            for (int cc = 0; cc < 2; cc++) {
                int j = 8 * nt + 2 * tg + cc;
                if (j < PPp) {
                    int jj1 = j / 7, jj2 = j - (j / 7) * 7;
                    float b0v = sbh[(ii0 - jj1 + 6) * 13 + (ij0 - jj2 + 6)];
                    float b1v = sbh[(ii1 - jj1 + 6) * 13 + (ij1 - jj2 + 6)];
                    sacc[nt][cc]     = sacc[nt][cc] * scale + b0v;
                    sacc[nt][2 + cc] = sacc[nt][2 + cc] * scale + b1v;
                    m0 = fmaxf(m0, sacc[nt][cc]);
                    m1 = fmaxf(m1, sacc[nt][2 + cc]);
                } else {
                    sacc[nt][cc] = -1e30f;
                    sacc[nt][2 + cc] = -1e30f;
                }
            }
        }
        m0 = fmaxf(m0, __shfl_xor_sync(0xFFFFFFFFu, m0, 1));
        m0 = fmaxf(m0, __shfl_xor_sync(0xFFFFFFFFu, m0, 2));
        m1 = fmaxf(m1, __shfl_xor_sync(0xFFFFFFFFu, m1, 1));
        m1 = fmaxf(m1, __shfl_xor_sync(0xFFFFFFFFu, m1, 2));

        float s0 = 0.f, s1 = 0.f;
#pragma unroll
        for (int nt = 0; nt < 8; nt++) {
#pragma unroll
            for (int cc = 0; cc < 2; cc++) {
                float e0 = __expf(sacc[nt][cc] - m0);
                float e1 = __expf(sacc[nt][2 + cc] - m1);
                sacc[nt][cc] = e0;
                sacc[nt][2 + cc] = e1;
                s0 += e0;
                s1 += e1;
            }
        }
        s0 += __shfl_xor_sync(0xFFFFFFFFu, s0, 1);
        s0 += __shfl_xor_sync(0xFFFFFFFFu, s0, 2);
        s1 += __shfl_xor_sync(0xFFFFFFFFu, s1, 1);
        s1 += __shfl_xor_sync(0xFFFFFFFFu, s1, 2);

        {
            uint32_t* pr0 = sp + r0 * SP_STR;
            uint32_t* pr1 = sp + r1 * SP_STR;
#pragma unroll
            for (int nt = 0; nt < 8; nt++) {
                int p = 4 * nt + tg;
                int pos = ((p >> 3) << 3) + pperm(p & 7);
                __half2 h0 = __floats2half2_rn(sacc[nt][0], sacc[nt][1]);
                __half2 h1 = __floats2half2_rn(sacc[nt][2], sacc[nt][3]);
                pr0[pos] = *(uint32_t*)&h0;
                pr1[pos] = *(uint32_t*)&h1;
            }
        }
        __syncwarp();

        float oacc[4][4];
#pragma unroll
        for (int nt = 0; nt < 4; nt++)
#pragma unroll
            for (int r = 0; r < 4; r++) oacc[nt][r] = 0.f;

        const uint32_t apb = (16 * wid + gp) * SP_STR + 2 * tg;
#pragma unroll
        for (int g = 0; g < 4; g++) {
            uint2 v0 = *(const uint2*)(sp + apb + g * 8);
            uint2 v1 = *(const uint2*)(sp + apb + 8 * SP_STR + g * 8);
#pragma unroll
            for (int nt = 0; nt < 4; nt++) {
                uint2 w = *(const uint2*)(svt + (8 * nt + gp) * SV_STR + 2 * tg + g * 8);
                mma_f16(oacc[nt], v0.x, v1.x, v0.y, v1.y, w.x, w.y);
            }
        }

        float inv0 = 1.f / s0, inv1 = 1.f / s1;
        if (r0 < PPp) {
            uint32_t* st = sq + r0 * SQ_STR;
#pragma unroll
            for (int nt = 0; nt < 4; nt++) {
                int p = 4 * nt + tg;
                int pos = ((p >> 3) << 3) + pperm(p & 7);
                __half2 h = __floats2half2_rn(oacc[nt][0] * inv0, oacc[nt][1] * inv0);
                st[pos] = *(uint32_t*)&h;
            }
        }
        if (r1 < PPp) {
            uint32_t* st = sq + r1 * SQ_STR;
#pragma unroll
            for (int nt = 0; nt < 4; nt++) {
                int p = 4 * nt + tg;
                int pos = ((p >> 3) << 3) + pperm(p & 7);
                __half2 h = __floats2half2_rn(oacc[nt][2] * inv1, oacc[nt][3] * inv1);
                st[pos] = *(uint32_t*)&h;
            }
        }
        __syncthreads();

        for (int idx = tid; idx < PPp * 4; idx += 128) {
            int r = idx >> 2, q4 = idx & 3;
            uint4 v = *(const uint4*)(sq + r * SQ_STR + 4 * q4);
            *(uint4*)(attn + (size_t)(base + r) * Cch + head * HDIM + 8 * q4) = v;
        }
    }
}

// ───────────────────────── launch ─────────────────────────
extern "C" void kernel_launch(void* const* d_in, const int* in_sizes, int n_in,
                              void* d_out, int out_size) {
    const float* x       = (const float*)d_in[0];
    const float* w_qkv   = (const float*)d_in[1];
    const float* b_qkv   = (const float*)d_in[2];
    const float* rel_pos = (const float*)d_in[3];
    const float* w_out   = (const float*)d_in[4];
    const float* b_out   = (const float*)d_in[5];
    float* out = (float*)d_out;

    __half *p_xw, *p_qkv, *p_attn, *p_out2, *p_wqkv, *p_wout;
    cudaGetSymbolAddress((void**)&p_xw, g_xw);
    cudaGetSymbolAddress((void**)&p_qkv, g_qkv);
    cudaGetSymbolAddress((void**)&p_attn, g_attn);
    cudaGetSymbolAddress((void**)&p_out2, g_out2);
    cudaGetSymbolAddress((void**)&p_wqkv, g_wqkv);
    cudaGetSymbolAddress((void**)&p_wout, g_wout);

    cudaFuncSetAttribute(k_gemm_f16, cudaFuncAttributeMaxDynamicSharedMemorySize, GEMM_SMEM);

    k_round<<<(576 * 192 + 255) / 256, 256>>>(w_qkv, p_wqkv, 576 * 192);
    k_round<<<(192 * 192 + 255) / 256, 256>>>(w_out, p_wout, 192 * 192);

    dim3 tb(32, 8);
    dim3 tg(HWSZ / 32, Cch / 32, Bsz);
    k_gather<<<tg, tb>>>(x, p_xw);
    k_gemm_f16<<<dim3(576 / GBN, Mrows / GBM), 256, GEMM_SMEM>>>(p_xw, p_wqkv, b_qkv, p_qkv, 576);
    k_attn_f16<<<740, 128>>>(p_qkv, p_attn, rel_pos);
    k_gemm_f16<<<dim3(192 / GBN, Mrows / GBM), 256, GEMM_SMEM>>>(p_attn, p_wout, b_out, p_out2, 192);
    k_scatter<<<tg, tb>>>(p_out2, out);
}

// round 17
// speedup vs baseline: 1.6250x; 1.0181x over previous
#include <cuda_runtime.h>
#include <cuda_fp16.h>
#include <cstdint>

#define Bsz   8
#define Cch   192
#define Himg  224
#define Wimg  224
#define Pw    7
#define NHEAD 6
#define HDIM  32
#define WGRID 32
#define NWIN  1024
#define PPp   49
#define Mrows 401408
#define HWSZ  50176
#define NPROB (Bsz * NWIN * NHEAD)

static __device__ __half g_xw[(size_t)Mrows * Cch];
static __device__ __half g_qkv[(size_t)Mrows * 3 * Cch];
static __device__ __half g_attn[(size_t)Mrows * Cch];
static __device__ __half g_out2[(size_t)Mrows * Cch];
static __device__ __half g_wqkv[576 * 192];
static __device__ __half g_wout[192 * 192];

__device__ __forceinline__ void mma_f16(float* c, uint32_t a0, uint32_t a1,
                                        uint32_t a2, uint32_t a3,
                                        uint32_t b0, uint32_t b1) {
    asm volatile(
        "mma.sync.aligned.m16n8k16.row.col.f32.f16.f16.f32 "
        "{%0,%1,%2,%3}, {%4,%5,%6,%7}, {%8,%9}, {%0,%1,%2,%3};"
        : "+f"(c[0]), "+f"(c[1]), "+f"(c[2]), "+f"(c[3])
        : "r"(a0), "r"(a1), "r"(a2), "r"(a3), "r"(b0), "r"(b1));
}
__device__ __forceinline__ void ldm_x4(uint32_t& r0, uint32_t& r1,
                                       uint32_t& r2, uint32_t& r3, uint32_t addr) {
    asm volatile("ldmatrix.sync.aligned.m8n8.x4.shared.b16 {%0,%1,%2,%3}, [%4];"
                 : "=r"(r0), "=r"(r1), "=r"(r2), "=r"(r3) : "r"(addr));
}
__device__ __forceinline__ void cp16(uint32_t dst, const void* src) {
    asm volatile("cp.async.cg.shared.global [%0], [%1], 16;" :: "r"(dst), "l"(src));
}
#define CP_COMMIT() asm volatile("cp.async.commit_group;" ::: "memory")
#define CP_WAIT(n)  asm volatile("cp.async.wait_group %0;" :: "n"(n) : "memory")

__global__ void k_round(const float* __restrict__ w, __half* __restrict__ o, int n) {
    int i = blockIdx.x * 256 + threadIdx.x;
    if (i < n) o[i] = __float2half_rn(w[i]);
}

// ───────────────────────── transposes ─────────────────────────
__device__ __forceinline__ int m_of(int b, int hw) {
    int h = hw / Wimg;
    int w = hw - h * Wimg;
    int wi = h / Pw, pi = h - wi * Pw;
    int wj = w / Pw, pj = w - wj * Pw;
    return ((b * WGRID + wi) * WGRID + wj) * PPp + pi * Pw + pj;
}

__global__ void k_gather(const float* __restrict__ x, __half* __restrict__ xw) {
    __shared__ float tile[32][33];
    int hw0 = blockIdx.x << 5, c0 = blockIdx.y << 5, b = blockIdx.z;
    int tx = threadIdx.x, ty = threadIdx.y;
    const float* xb = x + (size_t)b * Cch * HWSZ;
#pragma unroll
    for (int it = 0; it < 4; it++) {
        int c = c0 + ty + it * 8;
        tile[ty + it * 8][tx] = xb[(size_t)c * HWSZ + hw0 + tx];
    }
    __syncthreads();
#pragma unroll
    for (int it = 0; it < 4; it++) {
        int hw = hw0 + ty + it * 8;
        int m = m_of(b, hw);
        xw[(size_t)m * Cch + c0 + tx] = __float2half_rn(tile[tx][ty + it * 8]);
    }
}

__global__ void k_scatter(const __half* __restrict__ out2, float* __restrict__ out) {
    __shared__ float tile[32][33];
    int hw0 = blockIdx.x << 5, c0 = blockIdx.y << 5, b = blockIdx.z;
    int tx = threadIdx.x, ty = threadIdx.y;
#pragma unroll
    for (int it = 0; it < 4; it++) {
        int hw = hw0 + ty + it * 8;
        int m = m_of(b, hw);
        tile[ty + it * 8][tx] = __half2float(out2[(size_t)m * Cch + c0 + tx]);
    }
    __syncthreads();
    float* ob = out + (size_t)b * Cch * HWSZ;
#pragma unroll
    for (int it = 0; it < 4; it++) {
        int c = c0 + ty + it * 8;
        ob[(size_t)c * HWSZ + hw0 + tx] = tile[tx][ty + it * 8];
    }
}

// ───── FP16 GEMM: BM=128 BN=96 BK=32, ldmatrix fragments ─────
#define GBM 128
#define GBN 96
#define KTOT 192
#define KTILES 6
#define STRH 20                  // uints per row: 16 data + 4 pad (ldmatrix conflict-free)
#define A_U (GBM * STRH)         // 2560
#define B_U (GBN * STRH)         // 1920
#define GEMM_SMEM (2 * (A_U + B_U) * 4)   // 35840 B

__global__ void __launch_bounds__(256, 3)
k_gemm_f16(const __half* __restrict__ A, const __half* __restrict__ Wt,
           const float* __restrict__ bias, __half* __restrict__ C, int Ntot) {
    extern __shared__ uint32_t smu[];

    int tid = threadIdx.x;
    int wid = tid >> 5, lane = tid & 31;
    int gp = lane >> 2, tg = lane & 3;
    int wm = wid & 3, wn = wid >> 2;          // 4(M) x 2(N), warptile 32x48
    size_t bm = (size_t)blockIdx.y * GBM;
    int bn = blockIdx.x * GBN;

    uint32_t smb = (uint32_t)__cvta_generic_to_shared(smu);
    const uint32_t STG_B = (A_U + B_U) * 4;

#define LOAD_T(t, so) do {                                                    \
        int _k0 = (t) * 32;                                                   \
        _Pragma("unroll")                                                     \
        for (int u = 0; u < 2; u++) {                                         \
            int _idx = tid + 256 * u;                                         \
            int _r = _idx >> 2, _q = _idx & 3;                                \
            cp16(smb + (so) + (_r * STRH + _q * 4) * 4,                       \
                 A + (bm + _r) * KTOT + _k0 + _q * 8);                        \
        }                                                                     \
        _Pragma("unroll")                                                     \
        for (int u = 0; u < 2; u++) {                                         \
            int _idx = tid + 256 * u;                                         \
            if (_idx < GBN * 4) {                                             \
                int _r = _idx >> 2, _q = _idx & 3;                            \
                cp16(smb + (so) + (A_U + _r * STRH + _q * 4) * 4,             \
                     Wt + (size_t)(bn + _r) * KTOT + _k0 + _q * 8);           \
            }                                                                 \
        }                                                                     \
    } while (0)

    LOAD_T(0, 0);
    CP_COMMIT();

    float acc[2][6][4];
#pragma unroll
    for (int mt = 0; mt < 2; mt++)
#pragma unroll
        for (int nt = 0; nt < 6; nt++)
#pragma unroll
            for (int r = 0; r < 4; r++) acc[mt][nt][r] = 0.f;

    // ldmatrix lane addressing: row = lane&15, k-half = lane>>4
    const uint32_t lrow = (lane & 15), lkh = (lane >> 4);
    const uint32_t a_off = ((wm * 32 + lrow) * STRH) * 4 + lkh * 16;
    const uint32_t b_off = A_U * 4 + ((wn * 48 + lrow) * STRH) * 4 + lkh * 16;

#pragma unroll 1
    for (int t = 0; t < KTILES; t++) {
        if (t + 1 < KTILES) {
            LOAD_T(t + 1, ((t + 1) & 1) * STG_B);
            CP_COMMIT();
            CP_WAIT(1);
        } else {
            CP_WAIT(0);
        }
        __syncthreads();

        uint32_t sbase = smb + (t & 1) * STG_B;
#pragma unroll
        for (int g = 0; g < 2; g++) {
            uint32_t a[2][4], b[6][2];
#pragma unroll
            for (int mt = 0; mt < 2; mt++)
                ldm_x4(a[mt][0], a[mt][1], a[mt][2], a[mt][3],
                       sbase + a_off + mt * 16 * STRH * 4 + g * 32);
#pragma unroll
            for (int np = 0; np < 3; np++) {
                uint32_t t0, t1, t2, t3;
                ldm_x4(t0, t1, t2, t3,
                       sbase + b_off + np * 16 * STRH * 4 + g * 32);
                b[2 * np][0] = t0; b[2 * np][1] = t2;
                b[2 * np + 1][0] = t1; b[2 * np + 1][1] = t3;
            }
#pragma unroll
            for (int mt = 0; mt < 2; mt++)
#pragma unroll
                for (int nt = 0; nt < 6; nt++)
                    mma_f16(acc[mt][nt], a[mt][0], a[mt][1], a[mt][2], a[mt][3],
                            b[nt][0], b[nt][1]);
        }
        __syncthreads();
    }
#undef LOAD_T

#pragma unroll
    for (int mt = 0; mt < 2; mt++) {
        int row = (int)bm + wm * 32 + mt * 16 + gp;
#pragma unroll
        for (int nt = 0; nt < 6; nt++) {
            int col = bn + wn * 48 + nt * 8 + tg * 2;
            float b0 = bias[col], b1 = bias[col + 1];
            __half2 h0 = __floats2half2_rn(acc[mt][nt][0] + b0, acc[mt][nt][1] + b1);
            __half2 h1 = __floats2half2_rn(acc[mt][nt][2] + b0, acc[mt][nt][3] + b1);
            *(__half2*)(C + (size_t)row * Ntot + col) = h0;
            *(__half2*)(C + (size_t)(row + 8) * Ntot + col) = h1;
        }
    }
}

// ───── attention: persistent fp16 tensor-core, ldmatrix fragments ─────
#define SQ_STR 20     // 16 data uints + 4 pad
#define SV_STR 36     // 32 data uints + 4 pad
#define SP_STR 36

__global__ void __launch_bounds__(128)
k_attn_f16(const __half* __restrict__ qkv, __half* __restrict__ attn,
           const float* __restrict__ rel_pos) {
    __shared__ uint32_t sq[64 * SQ_STR];
    __shared__ uint32_t sk[64 * SQ_STR];
    __shared__ uint32_t svt[32 * SV_STR];
    __shared__ uint32_t sp[64 * SP_STR];
    __shared__ float ssb[NHEAD * 176];

    int tid = threadIdx.x;
    int wid = tid >> 5, lane = tid & 31;
    int gp = lane >> 2, tg = lane & 3;
    const float scale = 0.17677669529663687f;

    for (int i = tid; i < 15 * SQ_STR; i += 128) {
        sq[49 * SQ_STR + i] = 0u;
        sk[49 * SQ_STR + i] = 0u;
    }
    for (int i = tid; i < 32 * SV_STR; i += 128) svt[i] = 0u;
    for (int i = tid; i < NHEAD * 169; i += 128) {
        int h = i / 169, e = i - h * 169;
        ssb[h * 176 + e] = rel_pos[i];
    }

    const uint32_t lrow = (lane & 15), lkh = (lane >> 4);
    uint32_t smb_q = (uint32_t)__cvta_generic_to_shared(sq);
    uint32_t smb_k = (uint32_t)__cvta_generic_to_shared(sk);
    uint32_t smb_v = (uint32_t)__cvta_generic_to_shared(svt);
    uint32_t smb_p = (uint32_t)__cvta_generic_to_shared(sp);
    const uint32_t aq_off = ((16 * wid + lrow) * SQ_STR) * 4 + lkh * 16;
    const uint32_t ap_off = ((16 * wid + lrow) * SP_STR) * 4 + lkh * 16;

#pragma unroll 1
    for (int blk = blockIdx.x; blk < NPROB; blk += gridDim.x) {
        int head = blk % NHEAD;
        int win = blk / NHEAD;
        int base = win * PPp;
        const size_t rowb = (size_t)base * 576 + head * HDIM;

        __syncthreads();

        // stage Q/K (canonical) and V^T (d rows, canonical j)
        for (int idx = tid; idx < PPp * 4; idx += 128) {
            int r = idx >> 2, q4 = idx & 3;
            const __half* rowp = qkv + rowb + (size_t)r * 576;
            uint4 vq = *((const uint4*)rowp + q4);
            uint4 vk = *((const uint4*)(rowp + 192) + q4);
            uint4 vv = *((const uint4*)(rowp + 384) + q4);
            *(uint4*)(sq + r * SQ_STR + 4 * q4) = vq;
            *(uint4*)(sk + r * SQ_STR + 4 * q4) = vk;
            uint32_t va[4] = {vv.x, vv.y, vv.z, vv.w};
#pragma unroll
            for (int i2 = 0; i2 < 4; i2++) {
                int d0 = 8 * q4 + 2 * i2;
                __half2 hv = *(__half2*)&va[i2];
                ((__half*)(svt + d0 * SV_STR))[r] = __low2half(hv);
                ((__half*)(svt + (d0 + 1) * SV_STR))[r] = __high2half(hv);
            }
        }
        __syncthreads();

        // ---- S = Q K^T ----
        float sacc[8][4];
#pragma unroll
        for (int nt = 0; nt < 8; nt++)
#pragma unroll
            for (int r = 0; r < 4; r++) sacc[nt][r] = 0.f;

#pragma unroll
        for (int g = 0; g < 2; g++) {
            uint32_t a0, a1, a2, a3;
            ldm_x4(a0, a1, a2, a3, smb_q + aq_off + g * 32);
#pragma unroll
            for (int np = 0; np < 4; np++) {
                uint32_t t0, t1, t2, t3;
                ldm_x4(t0, t1, t2, t3,
                       smb_k + ((16 * np + lrow) * SQ_STR) * 4 + lkh * 16 + g * 32);
                mma_f16(sacc[2 * np], a0, a1, a2, a3, t0, t2);
                mma_f16(sacc[2 * np + 1], a0, a1, a2, a3, t1, t3);
            }
        }

        // ---- fragment softmax ----
        int r0 = 16 * wid + gp, r1 = r0 + 8;
        int i0 = (r0 < PPp) ? r0 : 0;
        int i1 = (r1 < PPp) ? r1 : 0;
        int ii0 = i0 / 7, ij0 = i0 - ii0 * 7;
        int ii1 = i1 / 7, ij1 = i1 - ii1 * 7;
        const float* sbh = ssb + head * 176;

        float m0 = -1e30f, m1 = -1e30f;
#pragma unroll
        for (int nt = 0; nt < 8; nt++) {
#pragma unroll
            for (int cc = 0; cc < 2; cc++) {
                int j = 8 * nt + 2 * tg + cc;
                if (j < PPp) {
                    int jj1 = j / 7, jj2 = j - (j / 7) * 7;
                    float b0v = sbh[(ii0 - jj1 + 6) * 13 + (ij0 - jj2 + 6)];
                    float b1v = sbh[(ii1 - jj1 + 6) * 13 + (ij1 - jj2 + 6)];
                    sacc[nt][cc]     = sacc[nt][cc] * scale + b0v;
                    sacc[nt][2 + cc] = sacc[nt][2 + cc] * scale + b1v;
                    m0 = fmaxf(m0, sacc[nt][cc]);
                    m1 = fmaxf(m1, sacc[nt][2 + cc]);
                } else {
                    sacc[nt][cc] = -1e30f;
                    sacc[nt][2 + cc] = -1e30f;
                }
            }
        }
        m0 = fmaxf(m0, __shfl_xor_sync(0xFFFFFFFFu, m0, 1));
        m0 = fmaxf(m0, __shfl_xor_sync(0xFFFFFFFFu, m0, 2));
        m1 = fmaxf(m1, __shfl_xor_sync(0xFFFFFFFFu, m1, 1));
        m1 = fmaxf(m1, __shfl_xor_sync(0xFFFFFFFFu, m1, 2));

        float s0 = 0.f, s1 = 0.f;
#pragma unroll
        for (int nt = 0; nt < 8; nt++) {
#pragma unroll
            for (int cc = 0; cc < 2; cc++) {
                float e0 = __expf(sacc[nt][cc] - m0);
                float e1 = __expf(sacc[nt][2 + cc] - m1);
                sacc[nt][cc] = e0;
                sacc[nt][2 + cc] = e1;
                s0 += e0;
                s1 += e1;
            }
        }
        s0 += __shfl_xor_sync(0xFFFFFFFFu, s0, 1);
        s0 += __shfl_xor_sync(0xFFFFFFFFu, s0, 2);
        s1 += __shfl_xor_sync(0xFFFFFFFFu, s1, 1);
        s1 += __shfl_xor_sync(0xFFFFFFFFu, s1, 2);

        // ---- store P (canonical half2 pairs) ----
        {
            uint32_t* pr0 = sp + r0 * SP_STR;
            uint32_t* pr1 = sp + r1 * SP_STR;
#pragma unroll
            for (int nt = 0; nt < 8; nt++) {
                int pos = 4 * nt + tg;
                __half2 h0 = __floats2half2_rn(sacc[nt][0], sacc[nt][1]);
                __half2 h1 = __floats2half2_rn(sacc[nt][2], sacc[nt][3]);
                pr0[pos] = *(uint32_t*)&h0;
                pr1[pos] = *(uint32_t*)&h1;
            }
        }
        __syncwarp();

        // ---- O = P V ----
        float oacc[4][4];
#pragma unroll
        for (int nt = 0; nt < 4; nt++)
#pragma unroll
            for (int r = 0; r < 4; r++) oacc[nt][r] = 0.f;

#pragma unroll
        for (int g = 0; g < 4; g++) {
            uint32_t a0, a1, a2, a3;
            ldm_x4(a0, a1, a2, a3, smb_p + ap_off + g * 32);
#pragma unroll
            for (int np = 0; np < 2; np++) {
                uint32_t t0, t1, t2, t3;
                ldm_x4(t0, t1, t2, t3,
                       smb_v + ((16 * np + lrow) * SV_STR) * 4 + lkh * 16 + g * 32);
                mma_f16(oacc[2 * np], a0, a1, a2, a3, t0, t2);
                mma_f16(oacc[2 * np + 1], a0, a1, a2, a3, t1, t3);
            }
        }

        // ---- stage O (canonical), coalesced out ----
        float inv0 = 1.f / s0, inv1 = 1.f / s1;
        if (r0 < PPp) {
            uint32_t* st = sq + r0 * SQ_STR;
#pragma unroll
            for (int nt = 0; nt < 4; nt++) {
                __half2 h = __floats2half2_rn(oacc[nt][0] * inv0, oacc[nt][1] * inv0);
                st[4 * nt + tg] = *(uint32_t*)&h;
            }
        }
        if (r1 < PPp) {
            uint32_t* st = sq + r1 * SQ_STR;
#pragma unroll
            for (int nt = 0; nt < 4; nt++) {
                __half2 h = __floats2half2_rn(oacc[nt][2] * inv1, oacc[nt][3] * inv1);
                st[4 * nt + tg] = *(uint32_t*)&h;
            }
        }
        __syncthreads();

        for (int idx = tid; idx < PPp * 4; idx += 128) {
            int r = idx >> 2, q4 = idx & 3;
            uint4 v = *(const uint4*)(sq + r * SQ_STR + 4 * q4);
            *(uint4*)(attn + (size_t)(base + r) * Cch + head * HDIM + 8 * q4) = v;
        }
    }
}

// ───────────────────────── launch ─────────────────────────
extern "C" void kernel_launch(void* const* d_in, const int* in_sizes, int n_in,
                              void* d_out, int out_size) {
    const float* x       = (const float*)d_in[0];
    const float* w_qkv   = (const float*)d_in[1];
    const float* b_qkv   = (const float*)d_in[2];
    const float* rel_pos = (const float*)d_in[3];
    const float* w_out   = (const float*)d_in[4];
    const float* b_out   = (const float*)d_in[5];
    float* out = (float*)d_out;

    __half *p_xw, *p_qkv, *p_attn, *p_out2, *p_wqkv, *p_wout;
    cudaGetSymbolAddress((void**)&p_xw, g_xw);
    cudaGetSymbolAddress((void**)&p_qkv, g_qkv);
    cudaGetSymbolAddress((void**)&p_attn, g_attn);
    cudaGetSymbolAddress((void**)&p_out2, g_out2);
    cudaGetSymbolAddress((void**)&p_wqkv, g_wqkv);
    cudaGetSymbolAddress((void**)&p_wout, g_wout);

    cudaFuncSetAttribute(k_gemm_f16, cudaFuncAttributeMaxDynamicSharedMemorySize, GEMM_SMEM);

    k_round<<<(576 * 192 + 255) / 256, 256>>>(w_qkv, p_wqkv, 576 * 192);
    k_round<<<(192 * 192 + 255) / 256, 256>>>(w_out, p_wout, 192 * 192);

    dim3 tb(32, 8);
    dim3 tg(HWSZ / 32, Cch / 32, Bsz);
    k_gather<<<tg, tb>>>(x, p_xw);
    k_gemm_f16<<<dim3(576 / GBN, Mrows / GBM), 256, GEMM_SMEM>>>(p_xw, p_wqkv, b_qkv, p_qkv, 576);
    k_attn_f16<<<740, 128>>>(p_qkv, p_attn, rel_pos);
    k_gemm_f16<<<dim3(192 / GBN, Mrows / GBM), 256, GEMM_SMEM>>>(p_attn, p_wout, b_out, p_out2, 192);
    k_scatter<<<tg, tb>>>(p_out2, out);
}